// round 16
// baseline (speedup 1.0000x reference)
#include <cuda_runtime.h>
#include <cuda_bf16.h>
#include <math.h>
#include <stdint.h>

#define N_ATOMS   30000
#define N_BONDS   100000
#define N_HALF    50000
#define N_ANGLES  200000
#define DDIM      128
#define HDIM      256
#define NLAYERS   8
#define K_BOND    20
#define K_ANGLE   32
#define KF        112
#define KF_USED   102

typedef unsigned long long ull;

__device__ float g_node[N_ATOMS * DDIM];
__device__ float g_edge0[N_BONDS * DDIM];
__device__ float g_half[N_HALF * DDIM];
__device__ float g_agg[N_ATOMS * DDIM];
__device__ float g_r_angle[(size_t)N_ANGLES * K_ANGLE];
__device__ float g_r_bond[(size_t)N_BONDS * K_BOND];
__device__ unsigned char g_wimg[16 * 262144];
__device__ float g_feat[(size_t)100000 * KF];
__device__ float g_wcatf[8 * KF * DDIM];
__device__ float g_bab[(size_t)100000 * DDIM];
__device__ int g_cnt[N_ATOMS];
__device__ int g_cur[N_ATOMS];
__device__ int g_rowptr[N_ATOMS + 1];
__device__ int g_csr_src[N_BONDS];
__device__ int g_csr_eid[N_BONDS];

__device__ __forceinline__ uint32_t pack_bf16(float a, float b) {
    uint32_t r;
    asm("cvt.rn.bf16x2.f32 %0, %1, %2;" : "=r"(r) : "f"(b), "f"(a));
    return r;
}
__device__ __forceinline__ float lo_f(uint32_t p) { return __uint_as_float(p << 16); }
__device__ __forceinline__ float hi_f(uint32_t p) { return __uint_as_float(p & 0xFFFF0000u); }

__device__ __forceinline__ ull pack2(float lo, float hi) {
    ull r; asm("mov.b64 %0, {%1, %2};" : "=l"(r) : "f"(lo), "f"(hi)); return r;
}
__device__ __forceinline__ void unpack2(ull v, float& lo, float& hi) {
    asm("mov.b64 {%0, %1}, %2;" : "=f"(lo), "=f"(hi) : "l"(v));
}
__device__ __forceinline__ void ffma2(ull& d, ull a, ull b) {
    asm("fma.rn.f32x2 %0, %1, %2, %0;" : "+l"(d) : "l"(a), "l"(b));
}

__device__ __forceinline__ void mma16816(float* d, uint32_t a0, uint32_t a1, uint32_t a2,
                                         uint32_t a3, uint32_t b0, uint32_t b1) {
    asm volatile(
        "mma.sync.aligned.m16n8k16.row.col.f32.bf16.bf16.f32 "
        "{%0,%1,%2,%3}, {%4,%5,%6,%7}, {%8,%9}, {%0,%1,%2,%3};"
        : "+f"(d[0]), "+f"(d[1]), "+f"(d[2]), "+f"(d[3])
        : "r"(a0), "r"(a1), "r"(a2), "r"(a3), "r"(b0), "r"(b1));
}
__device__ __forceinline__ void red_add_v4(float* p, float4 v) {
    asm volatile("red.global.add.v4.f32 [%0], {%1, %2, %3, %4};"
                 :: "l"(p), "f"(v.x), "f"(v.y), "f"(v.z), "f"(v.w) : "memory");
}
__device__ __forceinline__ void red_add_v2(float* p, float a, float b) {
    asm volatile("red.global.add.v2.f32 [%0], {%1, %2};" :: "l"(p), "f"(a), "f"(b) : "memory");
}
__device__ __forceinline__ void red_add1(float* p, float a) {
    asm volatile("red.global.add.f32 [%0], %1;" :: "l"(p), "f"(a) : "memory");
}

// mlp v2 smem layout (64 rows/CTA, 2 CTAs/SM)
// stage1: X(2x17408) + W1(2x34816) = 104448 B
// stage2: H1(2x33792) + W2(2x16896) = 101376 B
#define OFF_HB1   0
#define OFF_HB2   1024
#define OFF_HG    1536
#define OFF_HBT   2048
#define OFF_LNP   2560
#define ARENA     4096
#define M2_XHI    0
#define M2_XLO    17408
#define M2_W1HI   34816
#define M2_W1LO   69632
#define M2_H1HI   0
#define M2_H1LO   33792
#define M2_W2HI   67584
#define M2_W2LO   84480
#define ARENA_SZ  104448
#define MLP_SMEM  (ARENA + ARENA_SZ)

__global__ void zero4_kernel(float4* p, int n4) {
    int i = blockIdx.x * blockDim.x + threadIdx.x;
    if (i < n4) p[i] = make_float4(0.f, 0.f, 0.f, 0.f);
}
__global__ void zeroi_kernel(int* p, int n) {
    int i = blockIdx.x * blockDim.x + threadIdx.x;
    if (i < n) p[i] = 0;
}

__global__ void rbf_pre_kernel(const float* __restrict__ x, float* __restrict__ r, int n, int K) {
    int idx = blockIdx.x * blockDim.x + threadIdx.x;
    if (idx >= n * K) return;
    int row = idx / K;
    int k = idx - row * K;
    float d = x[row] - 0.1f * (float)k;
    r[idx] = expf(-10.f * d * d);
}

__global__ void node_embed_kernel(const int* __restrict__ atom_cat,
                                  const float* __restrict__ atom_emb,
                                  float* __restrict__ node) {
    int n = blockIdx.x;
    int d = threadIdx.x;
    float v = 0.f;
#pragma unroll
    for (int c = 0; c < 9; c++) {
        int cat = __ldg(&atom_cat[n * 9 + c]);
        v += __ldg(&atom_emb[((size_t)c * 64 + cat) * DDIM + d]);
    }
    node[(size_t)n * DDIM + d] = v;
}

__global__ __launch_bounds__(128) void bond_embed_kernel(
    const int* __restrict__ bond_cat, const float* __restrict__ rbond,
    const float* __restrict__ emb, const float* __restrict__ rbf_w,
    const float* __restrict__ rbf_b, float* __restrict__ out, int count) {
    __shared__ float rs[32][21];
    __shared__ int cats[32][3];
    int tid = threadIdx.x;
    int tx = tid & 31, ty = tid >> 5;
    int a0 = blockIdx.x * 32;
    for (int idx = tid; idx < 32 * K_BOND; idx += 128) {
        int a = idx / K_BOND, k = idx - a * K_BOND;
        int row = a0 + a;
        rs[a][k] = (row < count) ? __ldg(&rbond[(size_t)row * K_BOND + k]) : 0.f;
    }
    for (int idx = tid; idx < 96; idx += 128) {
        int a = idx / 3, c = idx - a * 3;
        int row = a0 + a;
        cats[a][c] = (row < count) ? __ldg(&bond_cat[(size_t)row * 3 + c]) : 0;
    }
    __syncthreads();
    float4 bv = __ldg(&((const float4*)rbf_b)[tx]);
    float acc[8][4];
#pragma unroll
    for (int i = 0; i < 8; i++) { acc[i][0] = bv.x; acc[i][1] = bv.y; acc[i][2] = bv.z; acc[i][3] = bv.w; }
    const float4* Wv = (const float4*)rbf_w;
#pragma unroll
    for (int k = 0; k < K_BOND; k++) {
        float4 w = __ldg(&Wv[k * 32 + tx]);
#pragma unroll
        for (int i = 0; i < 8; i++) {
            float rv = rs[ty * 8 + i][k];
            acc[i][0] += rv * w.x; acc[i][1] += rv * w.y;
            acc[i][2] += rv * w.z; acc[i][3] += rv * w.w;
        }
    }
#pragma unroll
    for (int i = 0; i < 8; i++) {
        int a = ty * 8 + i;
        int row = a0 + a;
        if (row >= count) continue;
        float4 v = make_float4(acc[i][0], acc[i][1], acc[i][2], acc[i][3]);
#pragma unroll
        for (int c = 0; c < 3; c++) {
            const float4* ev = (const float4*)(emb + ((size_t)c * 16 + cats[a][c]) * DDIM);
            float4 e4 = __ldg(&ev[tx]);
            v.x += e4.x; v.y += e4.y; v.z += e4.z; v.w += e4.w;
        }
        ((float4*)out)[(size_t)row * 32 + tx] = v;
    }
}

// ---------------- CSR build ----------------
__global__ void hist_kernel(const int* __restrict__ dst, int* __restrict__ cnt) {
    int e = blockIdx.x * blockDim.x + threadIdx.x;
    if (e < N_BONDS) atomicAdd(&cnt[__ldg(&dst[e])], 1);
}
__global__ __launch_bounds__(1024) void csr_scan_kernel(const int* __restrict__ cnt,
                                                        int* __restrict__ rowptr) {
    __shared__ int part[1024];
    int t = threadIdx.x;
    const int CH = (N_ATOMS + 1023) / 1024;
    int base = t * CH;
    int s = 0;
    for (int i = 0; i < CH; i++) {
        int idx = base + i;
        if (idx < N_ATOMS) s += cnt[idx];
    }
    part[t] = s;
    __syncthreads();
    for (int off = 1; off < 1024; off <<= 1) {
        int v = (t >= off) ? part[t - off] : 0;
        __syncthreads();
        part[t] += v;
        __syncthreads();
    }
    int run = (t == 0) ? 0 : part[t - 1];
    for (int i = 0; i < CH; i++) {
        int idx = base + i;
        if (idx < N_ATOMS) { rowptr[idx] = run; run += cnt[idx]; }
    }
    if (t == 1023) rowptr[N_ATOMS] = part[1023];
}
__global__ void csr_scatter_kernel(const int* __restrict__ src, const int* __restrict__ dst,
                                   const int* __restrict__ rowptr, int* __restrict__ cur,
                                   int* __restrict__ csr_src, int* __restrict__ csr_eid) {
    int e = blockIdx.x * blockDim.x + threadIdx.x;
    if (e >= N_BONDS) return;
    int d = __ldg(&dst[e]);
    int pos = __ldg(&rowptr[d]) + atomicAdd(&cur[d], 1);
    csr_src[pos] = __ldg(&src[e]);
    csr_eid[pos] = e;
}

__global__ __launch_bounds__(128) void csr_gather_kernel(
    const float* __restrict__ node, const float* __restrict__ edge,
    const int* __restrict__ rowptr, const int* __restrict__ csr_src,
    const int* __restrict__ csr_eid, float* __restrict__ agg, int shift) {
    int a = blockIdx.x * 4 + (threadIdx.x >> 5);
    int lane = threadIdx.x & 31;
    if (a >= N_ATOMS) return;
    int beg = __ldg(&rowptr[a]);
    int end = __ldg(&rowptr[a + 1]);
    float4 acc = make_float4(0.f, 0.f, 0.f, 0.f);
    for (int j = beg; j < end; j++) {
        int s = __ldg(&csr_src[j]);
        int e = __ldg(&csr_eid[j]);
        float4 nv = __ldg(&((const float4*)node)[(size_t)s * 32 + lane]);
        float4 ev = __ldg(&((const float4*)edge)[(size_t)(e >> shift) * 32 + lane]);
        acc.x += nv.x + ev.x; acc.y += nv.y + ev.y;
        acc.z += nv.z + ev.z; acc.w += nv.w + ev.w;
    }
    ((float4*)agg)[(size_t)a * 32 + lane] = acc;
}

// ---------------- BA feature build ----------------
__global__ void f1_build_kernel(const int* __restrict__ bond_cat,
                                const float* __restrict__ rbond,
                                float* __restrict__ feat) {
    int s = blockIdx.x * blockDim.x + threadIdx.x;
    if (s >= N_HALF) return;
    float* row = feat + (size_t)(50000 + s) * KF;
#pragma unroll
    for (int c = 0; c < 3; c++) {
        int v = __ldg(&bond_cat[(size_t)(2 * s) * 3 + c]);
        row[c * 16 + v] = 1.f;
    }
    const float4* rb = (const float4*)(rbond + (size_t)(2 * s) * K_BOND);
#pragma unroll
    for (int q = 0; q < 5; q++) ((float4*)(row + 48))[q] = __ldg(&rb[q]);
    row[100] = 1.f;
}

__global__ void fsum_scatter_kernel(const int* __restrict__ bond_cat,
                                    const float* __restrict__ rbond,
                                    const float* __restrict__ rangle,
                                    const int* __restrict__ src,
                                    const int* __restrict__ dst,
                                    float* __restrict__ feat) {
    int a = blockIdx.x * blockDim.x + threadIdx.x;
    if (a >= N_ANGLES) return;
    int s = __ldg(&src[a]);
    int d = __ldg(&dst[a]);
    float* row = feat + (size_t)d * KF;
#pragma unroll
    for (int c = 0; c < 3; c++) {
        int v = __ldg(&bond_cat[(size_t)(2 * s) * 3 + c]);
        red_add1(row + c * 16 + v, 1.f);
    }
    const float4* rb = (const float4*)(rbond + (size_t)(2 * s) * K_BOND);
#pragma unroll
    for (int q = 0; q < 5; q++) red_add_v4(row + 48 + q * 4, __ldg(&rb[q]));
    const float4* ra = (const float4*)(rangle + (size_t)a * K_ANGLE);
#pragma unroll
    for (int q = 0; q < 8; q++) red_add_v4(row + 68 + q * 4, __ldg(&ra[q]));
    red_add_v2(row + 100, 1.f, 1.f);
}

__global__ void wcat_prep_f32_kernel(const float* __restrict__ layer_bond_emb,
                                     const float* __restrict__ layer_bond_rbf_w,
                                     const float* __restrict__ layer_bond_rbf_b,
                                     const float* __restrict__ layer_angle_rbf_w,
                                     const float* __restrict__ layer_angle_rbf_b,
                                     float* __restrict__ wcat) {
    int gid = blockIdx.x * blockDim.x + threadIdx.x;
    if (gid >= 8 * KF * DDIM) return;
    int l = gid / (KF * DDIM);
    int r = gid % (KF * DDIM);
    int k = r / DDIM, n = r % DDIM;
    float v = 0.f;
    if (k < 48)        v = __ldg(&layer_bond_emb[(((size_t)l * 3 + (k >> 4)) * 16 + (k & 15)) * DDIM + n]);
    else if (k < 68)   v = __ldg(&layer_bond_rbf_w[((size_t)l * K_BOND + (k - 48)) * DDIM + n]);
    else if (k < 100)  v = __ldg(&layer_angle_rbf_w[((size_t)l * K_ANGLE + (k - 68)) * DDIM + n]);
    else if (k == 100) v = __ldg(&layer_bond_rbf_b[(size_t)l * DDIM + n]);
    else if (k == 101) v = __ldg(&layer_angle_rbf_b[(size_t)l * DDIM + n]);
    wcat[gid] = v;
}

// C[M,128] = A[M,112] @ Wcat (exact fp32, f32x2 FMA; Wcat is [k][n])
__global__ __launch_bounds__(256) void feat_gemm_f32_kernel(
    const float* __restrict__ A, const float* __restrict__ Wf,
    float* __restrict__ C, int M) {
    __shared__ float As[64 * KF];
    int tid = threadIdx.x;
    int tx = tid & 31, ty = tid >> 5;
    int row0 = blockIdx.x * 64;

    const float4* A4 = (const float4*)A;
    for (int i = tid; i < 64 * (KF / 4); i += 256) {
        int r = i / 28, c = i % 28;
        float4 v = make_float4(0.f, 0.f, 0.f, 0.f);
        if (row0 + r < M) v = __ldg(&A4[(size_t)(row0 + r) * 28 + c]);
        ((float4*)As)[r * 28 + c] = v;
    }
    __syncthreads();

    ull acc[8][2];
#pragma unroll
    for (int i = 0; i < 8; i++) { acc[i][0] = 0ull; acc[i][1] = 0ull; }

    const float4* W4 = (const float4*)Wf;
#pragma unroll 2
    for (int k = 0; k < KF_USED; k++) {
        float4 w = __ldg(&W4[k * 32 + tx]);
        ull w01 = pack2(w.x, w.y), w23 = pack2(w.z, w.w);
#pragma unroll
        for (int i = 0; i < 8; i++) {
            float a = As[(ty * 8 + i) * KF + k];
            ull aa = pack2(a, a);
            ffma2(acc[i][0], aa, w01);
            ffma2(acc[i][1], aa, w23);
        }
    }

#pragma unroll
    for (int i = 0; i < 8; i++) {
        int row = row0 + ty * 8 + i;
        if (row < M) {
            float o0, o1, o2, o3;
            unpack2(acc[i][0], o0, o1);
            unpack2(acc[i][1], o2, o3);
            ((float4*)C)[(size_t)row * 32 + tx] = make_float4(o0, o1, o2, o3);
        }
    }
}

// ---------------- tensor-core fused MLP + LN, 64 rows/CTA, 2 CTAs/SM ----------------
template <int DUP>
__global__ __launch_bounds__(256, 2) void mlp_mma_kernel(
    const float* __restrict__ X, const float* __restrict__ res,
    const float* __restrict__ b1, const float* __restrict__ b2,
    const float* __restrict__ lng, const float* __restrict__ lnb,
    const unsigned char* __restrict__ wimg,
    float* __restrict__ out, int N, float inv_sqrt_n,
    float* __restrict__ out_dup) {
    extern __shared__ unsigned char smem[];
    int tid = threadIdx.x;
    int wid = tid >> 5, lid = tid & 31;
    int gid = lid >> 2, tig = lid & 3;
    int row0 = blockIdx.x * 64;
    const int mwarp = wid >> 1, nwarp = wid & 1;
    const int rl = mwarp * 16 + gid;

    float* hb1 = (float*)(smem + OFF_HB1);
    float* hb2 = (float*)(smem + OFF_HB2);
    float* hg  = (float*)(smem + OFF_HG);
    float* hbt = (float*)(smem + OFF_HBT);
    float* lnp = (float*)(smem + OFF_LNP);
    hb1[tid] = __ldg(&b1[tid]);
    if (tid < 128) { hb2[tid] = __ldg(&b2[tid]); hg[tid] = __ldg(&lng[tid]); hbt[tid] = __ldg(&lnb[tid]); }

    // ---- X -> bf16 hi/lo planes (64 rows, stride 272 B) ----
    for (int t = tid; t < 1024; t += 256) {
        int r = t >> 4;
        int k0 = (t & 15) * 8;
        float4 f0 = make_float4(0.f, 0.f, 0.f, 0.f), f1 = f0;
        if (row0 + r < N) {
            const float4* xp = (const float4*)(X + (size_t)(row0 + r) * 128 + k0);
            f0 = __ldg(xp); f1 = __ldg(xp + 1);
        }
        float f[8] = {f0.x, f0.y, f0.z, f0.w, f1.x, f1.y, f1.z, f1.w};
        uint32_t ph[4], pl[4];
#pragma unroll
        for (int q = 0; q < 4; q++) {
            ph[q] = pack_bf16(f[2 * q], f[2 * q + 1]);
            pl[q] = pack_bf16(f[2 * q] - lo_f(ph[q]), f[2 * q + 1] - hi_f(ph[q]));
        }
        int byt = r * 272 + k0 * 2;
        *(uint4*)(smem + ARENA + M2_XHI + byt) = make_uint4(ph[0], ph[1], ph[2], ph[3]);
        *(uint4*)(smem + ARENA + M2_XLO + byt) = make_uint4(pl[0], pl[1], pl[2], pl[3]);
    }

    // ---- stage 1: two 128-col W1 chunks ----
    float acc[2][8][4];
#pragma unroll
    for (int nc = 0; nc < 2; nc++)
#pragma unroll
        for (int ns = 0; ns < 8; ns++)
#pragma unroll
            for (int q = 0; q < 4; q++) acc[nc][ns][q] = 0.f;

#pragma unroll 1
    for (int nc = 0; nc < 2; nc++) {
        if (nc) __syncthreads();
        for (int i = tid; i < 2048; i += 256) {
            int n = i >> 4, c = i & 15;
            int dst = n * 272 + c * 16;
            *(uint4*)(smem + ARENA + M2_W1HI + dst) =
                __ldg(&((const uint4*)wimg)[(nc * 128 + n) * 16 + c]);
            *(uint4*)(smem + ARENA + M2_W1LO + dst) =
                __ldg(&((const uint4*)(wimg + 65536))[(nc * 128 + n) * 16 + c]);
        }
        __syncthreads();
#pragma unroll 1
        for (int pass = 0; pass < 3; pass++) {
            const uint32_t* Ap = (const uint32_t*)(smem + ARENA + (pass == 2 ? M2_XLO : M2_XHI));
            const uint32_t* Bp = (const uint32_t*)(smem + ARENA + (pass == 1 ? M2_W1LO : M2_W1HI));
#pragma unroll
            for (int k16 = 0; k16 < 8; k16++) {
                int kw = k16 * 8 + tig;
                const uint32_t* r0p = Ap + rl * 68 + kw;
                uint32_t a0 = r0p[0], a1 = r0p[8 * 68], a2 = r0p[4], a3 = r0p[8 * 68 + 4];
#pragma unroll
                for (int ns = 0; ns < 8; ns++) {
                    const uint32_t* br = Bp + (nwarp * 64 + ns * 8 + gid) * 68 + kw;
                    mma16816(acc[nc][ns], a0, a1, a2, a3, br[0], br[4]);
                }
            }
        }
    }
    __syncthreads();

    // ---- epilogue 1: relu(+b1) -> H1 planes (stride 528 B) ----
    {
        uint32_t* Hh = (uint32_t*)(smem + ARENA + M2_H1HI);
        uint32_t* Hl = (uint32_t*)(smem + ARENA + M2_H1LO);
#pragma unroll
        for (int nc = 0; nc < 2; nc++)
#pragma unroll
            for (int ns = 0; ns < 8; ns++) {
                int c0 = nc * 128 + nwarp * 64 + ns * 8 + 2 * tig;
                float bb0 = hb1[c0], bb1 = hb1[c0 + 1];
                float v0 = fmaxf(acc[nc][ns][0] + bb0, 0.f);
                float v1 = fmaxf(acc[nc][ns][1] + bb1, 0.f);
                float v2 = fmaxf(acc[nc][ns][2] + bb0, 0.f);
                float v3 = fmaxf(acc[nc][ns][3] + bb1, 0.f);
                uint32_t p0 = pack_bf16(v0, v1);
                uint32_t q0 = pack_bf16(v0 - lo_f(p0), v1 - hi_f(p0));
                uint32_t p1 = pack_bf16(v2, v3);
                uint32_t q1 = pack_bf16(v2 - lo_f(p1), v3 - hi_f(p1));
                Hh[rl * 132 + (c0 >> 1)] = p0;
                Hl[rl * 132 + (c0 >> 1)] = q0;
                Hh[(rl + 8) * 132 + (c0 >> 1)] = p1;
                Hl[(rl + 8) * 132 + (c0 >> 1)] = q1;
            }
    }

    // ---- stage 2: four 32-col W2 chunks ----
    float acc2[4][2][4];
#pragma unroll
    for (int wc = 0; wc < 4; wc++)
#pragma unroll
        for (int ns = 0; ns < 2; ns++)
#pragma unroll
            for (int q = 0; q < 4; q++) acc2[wc][ns][q] = 0.f;

#pragma unroll 1
    for (int wc = 0; wc < 4; wc++) {
        __syncthreads();
        for (int i = tid; i < 1024; i += 256) {
            int n = i >> 5, c = i & 31;
            int dst = n * 528 + c * 16;
            *(uint4*)(smem + ARENA + M2_W2HI + dst) =
                __ldg(&((const uint4*)(wimg + 131072))[(wc * 32 + n) * 32 + c]);
            *(uint4*)(smem + ARENA + M2_W2LO + dst) =
                __ldg(&((const uint4*)(wimg + 196608))[(wc * 32 + n) * 32 + c]);
        }
        __syncthreads();
#pragma unroll 1
        for (int pass = 0; pass < 3; pass++) {
            const uint32_t* Ap = (const uint32_t*)(smem + ARENA + (pass == 2 ? M2_H1LO : M2_H1HI));
            const uint32_t* Bp = (const uint32_t*)(smem + ARENA + (pass == 1 ? M2_W2LO : M2_W2HI));
#pragma unroll
            for (int k16 = 0; k16 < 16; k16++) {
                int kw = k16 * 8 + tig;
                const uint32_t* r0p = Ap + rl * 132 + kw;
                uint32_t a0 = r0p[0], a1 = r0p[8 * 132], a2 = r0p[4], a3 = r0p[8 * 132 + 4];
#pragma unroll
                for (int ns = 0; ns < 2; ns++) {
                    const uint32_t* br = Bp + (nwarp * 16 + ns * 8 + gid) * 132 + kw;
                    mma16816(acc2[wc][ns], a0, a1, a2, a3, br[0], br[4]);
                }
            }
        }
    }

    // ---- +b2, LN partials (quad shfl + cross-warp smem) ----
    float s0 = 0.f, q0 = 0.f, s1 = 0.f, q1 = 0.f;
#pragma unroll
    for (int wc = 0; wc < 4; wc++)
#pragma unroll
        for (int ns = 0; ns < 2; ns++) {
            int c0 = wc * 32 + nwarp * 16 + ns * 8 + 2 * tig;
            acc2[wc][ns][0] += hb2[c0];
            acc2[wc][ns][1] += hb2[c0 + 1];
            acc2[wc][ns][2] += hb2[c0];
            acc2[wc][ns][3] += hb2[c0 + 1];
            s0 += acc2[wc][ns][0] + acc2[wc][ns][1];
            q0 += acc2[wc][ns][0] * acc2[wc][ns][0] + acc2[wc][ns][1] * acc2[wc][ns][1];
            s1 += acc2[wc][ns][2] + acc2[wc][ns][3];
            q1 += acc2[wc][ns][2] * acc2[wc][ns][2] + acc2[wc][ns][3] * acc2[wc][ns][3];
        }
#pragma unroll
    for (int off = 1; off <= 2; off <<= 1) {
        s0 += __shfl_xor_sync(0xffffffffu, s0, off);
        q0 += __shfl_xor_sync(0xffffffffu, q0, off);
        s1 += __shfl_xor_sync(0xffffffffu, s1, off);
        q1 += __shfl_xor_sync(0xffffffffu, q1, off);
    }
    if (tig == 0) {
        lnp[rl * 4 + nwarp * 2]           = s0;
        lnp[rl * 4 + nwarp * 2 + 1]       = q0;
        lnp[(rl + 8) * 4 + nwarp * 2]     = s1;
        lnp[(rl + 8) * 4 + nwarp * 2 + 1] = q1;
    }
    __syncthreads();
    float S0 = lnp[rl * 4] + lnp[rl * 4 + 2];
    float Q0 = lnp[rl * 4 + 1] + lnp[rl * 4 + 3];
    float S1 = lnp[(rl + 8) * 4] + lnp[(rl + 8) * 4 + 2];
    float Q1 = lnp[(rl + 8) * 4 + 1] + lnp[(rl + 8) * 4 + 3];
    float mu0 = S0 * (1.f / 128.f), mu1 = S1 * (1.f / 128.f);
    float rs0 = rsqrtf(Q0 * (1.f / 128.f) - mu0 * mu0 + 1e-5f);
    float rs1 = rsqrtf(Q1 * (1.f / 128.f) - mu1 * mu1 + 1e-5f);

    int rlo = row0 + rl, rhi = rlo + 8;
    const float2* res2 = (const float2*)res;
    float2* out2 = (float2*)out;
    float2* dup2 = (float2*)out_dup;
#pragma unroll
    for (int wc = 0; wc < 4; wc++)
#pragma unroll
        for (int ns = 0; ns < 2; ns++) {
            int c0 = wc * 32 + nwarp * 16 + ns * 8 + 2 * tig;
            float g0 = hg[c0], g1 = hg[c0 + 1], t0 = hbt[c0], t1 = hbt[c0 + 1];
            if (rlo < N) {
                float2 rr = __ldg(&res2[(size_t)rlo * 64 + (c0 >> 1)]);
                float o0 = fmaxf(((acc2[wc][ns][0] - mu0) * rs0 * g0 + t0) * inv_sqrt_n, 0.f) + rr.x;
                float o1 = fmaxf(((acc2[wc][ns][1] - mu0) * rs0 * g1 + t1) * inv_sqrt_n, 0.f) + rr.y;
                float2 ov = make_float2(o0, o1);
                out2[(size_t)rlo * 64 + (c0 >> 1)] = ov;
                if (DUP) {
                    dup2[(size_t)(2 * rlo) * 64 + (c0 >> 1)] = ov;
                    dup2[(size_t)(2 * rlo + 1) * 64 + (c0 >> 1)] = ov;
                }
            }
            if (rhi < N) {
                float2 rr = __ldg(&res2[(size_t)rhi * 64 + (c0 >> 1)]);
                float o2 = fmaxf(((acc2[wc][ns][2] - mu1) * rs1 * g0 + t0) * inv_sqrt_n, 0.f) + rr.x;
                float o3 = fmaxf(((acc2[wc][ns][3] - mu1) * rs1 * g1 + t1) * inv_sqrt_n, 0.f) + rr.y;
                float2 ov = make_float2(o2, o3);
                out2[(size_t)rhi * 64 + (c0 >> 1)] = ov;
                if (DUP) {
                    dup2[(size_t)(2 * rhi) * 64 + (c0 >> 1)] = ov;
                    dup2[(size_t)(2 * rhi + 1) * 64 + (c0 >> 1)] = ov;
                }
            }
        }
}

__global__ void graph_zero_kernel(float* g) { g[threadIdx.x] = 0.f; }

__global__ void graph_mean_kernel(const float* __restrict__ node, float* __restrict__ g) {
    int d = threadIdx.x;
    int r0 = blockIdx.x * 125;
    float s = 0.f;
    for (int i = 0; i < 125; i++) s += node[(size_t)(r0 + i) * DDIM + d];
    atomicAdd(&g[d], s * (1.f / 30000.f));
}

__global__ void wprep_kernel(const float* __restrict__ ab_w1, const float* __restrict__ ab_w2,
                             const float* __restrict__ ba_w1, const float* __restrict__ ba_w2,
                             unsigned char* __restrict__ wimg) {
    int gid = blockIdx.x * blockDim.x + threadIdx.x;
    if (gid >= 16 * 65536) return;
    int mlp = gid >> 16;
    int e = gid & 65535;
    int is_ba = mlp >= 8, l = mlp & 7;
    int is_w2 = e >= 32768;
    int e2 = e & 32767;
    float v;
    int dstoff;
    if (!is_w2) {
        int n = e2 >> 7, k = e2 & 127;
        const float* W = (is_ba ? ba_w1 : ab_w1) + (size_t)l * DDIM * HDIM;
        v = __ldg(&W[(size_t)k * HDIM + n]);
        dstoff = n * 128 + k;
    } else {
        int n = e2 >> 8, k = e2 & 255;
        const float* W = (is_ba ? ba_w2 : ab_w2) + (size_t)l * HDIM * DDIM;
        v = __ldg(&W[(size_t)k * DDIM + n]);
        dstoff = n * 256 + k;
    }
    __nv_bfloat16 hi = __float2bfloat16(v);
    __nv_bfloat16 lo = __float2bfloat16(v - __bfloat162float(hi));
    unsigned char* base = wimg + (size_t)mlp * 262144 + (is_w2 ? 131072 : 0);
    *(__nv_bfloat16*)(base + dstoff * 2)         = hi;
    *(__nv_bfloat16*)(base + 65536 + dstoff * 2) = lo;
}

// ---------------- host ----------------
extern "C" void kernel_launch(void* const* d_in, const int* in_sizes, int n_in,
                              void* d_out, int out_size) {
    const int*   atom_cat          = (const int*)d_in[0];
    const int*   bond_cat          = (const int*)d_in[1];
    const float* bond_float        = (const float*)d_in[2];
    const float* angle_float       = (const float*)d_in[3];
    const int*   ab_src            = (const int*)d_in[4];
    const int*   ab_dst            = (const int*)d_in[5];
    const int*   ba_src            = (const int*)d_in[6];
    const int*   ba_dst            = (const int*)d_in[7];
    const float* atom_emb          = (const float*)d_in[8];
    const float* bond_emb_init     = (const float*)d_in[9];
    const float* bond_rbf_w_init   = (const float*)d_in[10];
    const float* bond_rbf_b_init   = (const float*)d_in[11];
    const float* layer_bond_emb    = (const float*)d_in[12];
    const float* layer_bond_rbf_w  = (const float*)d_in[13];
    const float* layer_bond_rbf_b  = (const float*)d_in[14];
    const float* layer_angle_rbf_w = (const float*)d_in[15];
    const float* layer_angle_rbf_b = (const float*)d_in[16];
    const float* ab_w1 = (const float*)d_in[17];
    const float* ab_b1 = (const float*)d_in[18];
    const float* ab_w2 = (const float*)d_in[19];
    const float* ab_b2 = (const float*)d_in[20];
    const float* ab_ln_g = (const float*)d_in[21];
    const float* ab_ln_b = (const float*)d_in[22];
    const float* ba_w1 = (const float*)d_in[23];
    const float* ba_b1 = (const float*)d_in[24];
    const float* ba_w2 = (const float*)d_in[25];
    const float* ba_b2 = (const float*)d_in[26];
    const float* ba_ln_g = (const float*)d_in[27];
    const float* ba_ln_b = (const float*)d_in[28];

    float *node, *edge0, *half, *agg, *r_angle, *r_bond, *feat, *bab, *wcatf;
    unsigned char *wimg;
    int *cnt, *cur, *rowptr, *csr_src, *csr_eid;
    cudaGetSymbolAddress((void**)&node,    g_node);
    cudaGetSymbolAddress((void**)&edge0,   g_edge0);
    cudaGetSymbolAddress((void**)&half,    g_half);
    cudaGetSymbolAddress((void**)&agg,     g_agg);
    cudaGetSymbolAddress((void**)&r_angle, g_r_angle);
    cudaGetSymbolAddress((void**)&r_bond,  g_r_bond);
    cudaGetSymbolAddress((void**)&wimg,    g_wimg);
    cudaGetSymbolAddress((void**)&feat,    g_feat);
    cudaGetSymbolAddress((void**)&wcatf,   g_wcatf);
    cudaGetSymbolAddress((void**)&bab,     g_bab);
    cudaGetSymbolAddress((void**)&cnt,     g_cnt);
    cudaGetSymbolAddress((void**)&cur,     g_cur);
    cudaGetSymbolAddress((void**)&rowptr,  g_rowptr);
    cudaGetSymbolAddress((void**)&csr_src, g_csr_src);
    cudaGetSymbolAddress((void**)&csr_eid, g_csr_eid);

    cudaFuncSetAttribute(mlp_mma_kernel<0>, cudaFuncAttributeMaxDynamicSharedMemorySize, MLP_SMEM);
    cudaFuncSetAttribute(mlp_mma_kernel<1>, cudaFuncAttributeMaxDynamicSharedMemorySize, MLP_SMEM);

    const float inv_a = 1.0f / sqrtf((float)N_ATOMS);
    const float inv_h = 1.0f / sqrtf((float)N_HALF);

    // ---- one-time prep ----
    wprep_kernel<<<4096, 256>>>(ab_w1, ab_w2, ba_w1, ba_w2, wimg);
    rbf_pre_kernel<<<(N_ANGLES * K_ANGLE + 255) / 256, 256>>>(angle_float, r_angle, N_ANGLES, K_ANGLE);
    rbf_pre_kernel<<<(N_BONDS * K_BOND + 255) / 256, 256>>>(bond_float, r_bond, N_BONDS, K_BOND);
    node_embed_kernel<<<N_ATOMS, 128>>>(atom_cat, atom_emb, node);
    bond_embed_kernel<<<(N_BONDS + 31) / 32, 128>>>(bond_cat, r_bond, bond_emb_init,
                                                    bond_rbf_w_init, bond_rbf_b_init,
                                                    edge0, N_BONDS);
    zeroi_kernel<<<(N_ATOMS + 255) / 256, 256>>>(cnt, N_ATOMS);
    zeroi_kernel<<<(N_ATOMS + 255) / 256, 256>>>(cur, N_ATOMS);
    hist_kernel<<<(N_BONDS + 255) / 256, 256>>>(ab_dst, cnt);
    csr_scan_kernel<<<1, 1024>>>(cnt, rowptr);
    csr_scatter_kernel<<<(N_BONDS + 255) / 256, 256>>>(ab_src, ab_dst, rowptr, cur,
                                                       csr_src, csr_eid);
    zero4_kernel<<<(100000 * KF / 4 + 255) / 256, 256>>>((float4*)feat, 100000 * KF / 4);
    f1_build_kernel<<<(N_HALF + 255) / 256, 256>>>(bond_cat, r_bond, feat);
    fsum_scatter_kernel<<<(N_ANGLES + 127) / 128, 128>>>(bond_cat, r_bond, r_angle,
                                                         ba_src, ba_dst, feat);
    wcat_prep_f32_kernel<<<(8 * KF * DDIM + 255) / 256, 256>>>(
        layer_bond_emb, layer_bond_rbf_w, layer_bond_rbf_b,
        layer_angle_rbf_w, layer_angle_rbf_b, wcatf);

    float* out = (float*)d_out;
    float* out_node = out;
    float* out_edge = out + (size_t)N_ATOMS * DDIM;
    for (int l = 0; l < NLAYERS; l++) {
        // --- AB GNN: CSR gather + MLP ---
        csr_gather_kernel<<<(N_ATOMS + 3) / 4, 128>>>(
            node, (l == 0) ? edge0 : half, rowptr, csr_src, csr_eid,
            agg, (l == 0) ? 0 : 1);
        mlp_mma_kernel<0><<<(N_ATOMS + 63) / 64, 256, MLP_SMEM>>>(
            agg, node,
            ab_b1 + (size_t)l * HDIM, ab_b2 + (size_t)l * DDIM,
            ab_ln_g + (size_t)l * DDIM, ab_ln_b + (size_t)l * DDIM,
            wimg + (size_t)l * 262144,
            (l == NLAYERS - 1) ? out_node : node, N_ATOMS, inv_a, nullptr);

        // --- BA GNN: feature GEMM + MLP (dup-out instantiation on last layer) ---
        feat_gemm_f32_kernel<<<(100000 + 63) / 64, 256>>>(
            feat, wcatf + (size_t)l * KF * DDIM, bab, 100000);
        if (l == NLAYERS - 1) {
            mlp_mma_kernel<1><<<(N_HALF + 63) / 64, 256, MLP_SMEM>>>(
                bab, bab + (size_t)50000 * DDIM,
                ba_b1 + (size_t)l * HDIM, ba_b2 + (size_t)l * DDIM,
                ba_ln_g + (size_t)l * DDIM, ba_ln_b + (size_t)l * DDIM,
                wimg + (size_t)(8 + l) * 262144,
                half, N_HALF, inv_h, out_edge);
        } else {
            mlp_mma_kernel<0><<<(N_HALF + 63) / 64, 256, MLP_SMEM>>>(
                bab, bab + (size_t)50000 * DDIM,
                ba_b1 + (size_t)l * HDIM, ba_b2 + (size_t)l * DDIM,
                ba_ln_g + (size_t)l * DDIM, ba_ln_b + (size_t)l * DDIM,
                wimg + (size_t)(8 + l) * 262144,
                half, N_HALF, inv_h, nullptr);
        }
    }

    // --- graph mean (reads node result from d_out) ---
    float* gout = out + (size_t)N_ATOMS * DDIM + (size_t)N_BONDS * DDIM;
    graph_zero_kernel<<<1, 128>>>(gout);
    graph_mean_kernel<<<240, 128>>>(out_node, gout);
}

// round 17
// speedup vs baseline: 1.3389x; 1.3389x over previous
#include <cuda_runtime.h>
#include <cuda_bf16.h>
#include <math.h>
#include <stdint.h>

#define N_ATOMS   30000
#define N_BONDS   100000
#define N_HALF    50000
#define N_ANGLES  200000
#define DDIM      128
#define HDIM      256
#define NLAYERS   8
#define K_BOND    20
#define K_ANGLE   32
#define KF        112

typedef unsigned long long ull;

__device__ float g_node[N_ATOMS * DDIM];
__device__ float g_edge0[N_BONDS * DDIM];
__device__ float g_half[N_HALF * DDIM];
__device__ float g_agg[N_ATOMS * DDIM];
__device__ float g_r_angle[(size_t)N_ANGLES * K_ANGLE];
__device__ float g_r_bond[(size_t)N_BONDS * K_BOND];
__device__ unsigned char g_wimg[16 * 262144];
__device__ float g_feat[(size_t)100000 * KF];
__device__ float g_wcatn[8 * 128 * KF];           // fp32 Wcat^T [l][n][k]
__device__ float g_bab[(size_t)100000 * DDIM];
__device__ int g_cnt[N_ATOMS];
__device__ int g_cur[N_ATOMS];
__device__ int g_rowptr[N_ATOMS + 1];
__device__ int g_csr_src[N_BONDS];
__device__ int g_csr_eid[N_BONDS];

__device__ __forceinline__ uint32_t pack_bf16(float a, float b) {
    uint32_t r;
    asm("cvt.rn.bf16x2.f32 %0, %1, %2;" : "=r"(r) : "f"(b), "f"(a));
    return r;
}
__device__ __forceinline__ float lo_f(uint32_t p) { return __uint_as_float(p << 16); }
__device__ __forceinline__ float hi_f(uint32_t p) { return __uint_as_float(p & 0xFFFF0000u); }

__device__ __forceinline__ void mma16816(float* d, uint32_t a0, uint32_t a1, uint32_t a2,
                                         uint32_t a3, uint32_t b0, uint32_t b1) {
    asm volatile(
        "mma.sync.aligned.m16n8k16.row.col.f32.bf16.bf16.f32 "
        "{%0,%1,%2,%3}, {%4,%5,%6,%7}, {%8,%9}, {%0,%1,%2,%3};"
        : "+f"(d[0]), "+f"(d[1]), "+f"(d[2]), "+f"(d[3])
        : "r"(a0), "r"(a1), "r"(a2), "r"(a3), "r"(b0), "r"(b1));
}
__device__ __forceinline__ void red_add_v4(float* p, float4 v) {
    asm volatile("red.global.add.v4.f32 [%0], {%1, %2, %3, %4};"
                 :: "l"(p), "f"(v.x), "f"(v.y), "f"(v.z), "f"(v.w) : "memory");
}
__device__ __forceinline__ void red_add_v2(float* p, float a, float b) {
    asm volatile("red.global.add.v2.f32 [%0], {%1, %2};" :: "l"(p), "f"(a), "f"(b) : "memory");
}
__device__ __forceinline__ void red_add1(float* p, float a) {
    asm volatile("red.global.add.f32 [%0], %1;" :: "l"(p), "f"(a) : "memory");
}

// mlp smem (bytes) — R14 layout, 128 rows/CTA, 1 CTA/SM
#define OFF_HB1   0
#define OFF_HB2   1024
#define OFF_HG    1536
#define OFF_HBT   2048
#define ARENA     4096
#define OFF_XHI   0
#define OFF_XLO   34816
#define OFF_W1HI  69632
#define OFF_W1LO  139264
#define OFF_H1HI  0
#define OFF_H1LO  67584
#define OFF_W2HI  135168
#define OFF_W2LO  168960
#define MLP_SMEM  (ARENA + 208896)
// feat_mma smem (stride 60 words)
#define FM_AHI    0
#define FM_ALO    30720
#define FM_BHI    61440
#define FM_BLO    76800
#define FM_SMEM   92160

__global__ void zero4_kernel(float4* p, int n4) {
    int i = blockIdx.x * blockDim.x + threadIdx.x;
    if (i < n4) p[i] = make_float4(0.f, 0.f, 0.f, 0.f);
}
__global__ void zeroi_kernel(int* p, int n) {
    int i = blockIdx.x * blockDim.x + threadIdx.x;
    if (i < n) p[i] = 0;
}

__global__ void rbf_pre_kernel(const float* __restrict__ x, float* __restrict__ r, int n, int K) {
    int idx = blockIdx.x * blockDim.x + threadIdx.x;
    if (idx >= n * K) return;
    int row = idx / K;
    int k = idx - row * K;
    float d = x[row] - 0.1f * (float)k;
    r[idx] = expf(-10.f * d * d);
}

__global__ void node_embed_kernel(const int* __restrict__ atom_cat,
                                  const float* __restrict__ atom_emb,
                                  float* __restrict__ node) {
    int n = blockIdx.x;
    int d = threadIdx.x;
    float v = 0.f;
#pragma unroll
    for (int c = 0; c < 9; c++) {
        int cat = __ldg(&atom_cat[n * 9 + c]);
        v += __ldg(&atom_emb[((size_t)c * 64 + cat) * DDIM + d]);
    }
    node[(size_t)n * DDIM + d] = v;
}

__global__ __launch_bounds__(128) void bond_embed_kernel(
    const int* __restrict__ bond_cat, const float* __restrict__ rbond,
    const float* __restrict__ emb, const float* __restrict__ rbf_w,
    const float* __restrict__ rbf_b, float* __restrict__ out, int count) {
    __shared__ float rs[32][21];
    __shared__ int cats[32][3];
    int tid = threadIdx.x;
    int tx = tid & 31, ty = tid >> 5;
    int a0 = blockIdx.x * 32;
    for (int idx = tid; idx < 32 * K_BOND; idx += 128) {
        int a = idx / K_BOND, k = idx - a * K_BOND;
        int row = a0 + a;
        rs[a][k] = (row < count) ? __ldg(&rbond[(size_t)row * K_BOND + k]) : 0.f;
    }
    for (int idx = tid; idx < 96; idx += 128) {
        int a = idx / 3, c = idx - a * 3;
        int row = a0 + a;
        cats[a][c] = (row < count) ? __ldg(&bond_cat[(size_t)row * 3 + c]) : 0;
    }
    __syncthreads();
    float4 bv = __ldg(&((const float4*)rbf_b)[tx]);
    float acc[8][4];
#pragma unroll
    for (int i = 0; i < 8; i++) { acc[i][0] = bv.x; acc[i][1] = bv.y; acc[i][2] = bv.z; acc[i][3] = bv.w; }
    const float4* Wv = (const float4*)rbf_w;
#pragma unroll
    for (int k = 0; k < K_BOND; k++) {
        float4 w = __ldg(&Wv[k * 32 + tx]);
#pragma unroll
        for (int i = 0; i < 8; i++) {
            float rv = rs[ty * 8 + i][k];
            acc[i][0] += rv * w.x; acc[i][1] += rv * w.y;
            acc[i][2] += rv * w.z; acc[i][3] += rv * w.w;
        }
    }
#pragma unroll
    for (int i = 0; i < 8; i++) {
        int a = ty * 8 + i;
        int row = a0 + a;
        if (row >= count) continue;
        float4 v = make_float4(acc[i][0], acc[i][1], acc[i][2], acc[i][3]);
#pragma unroll
        for (int c = 0; c < 3; c++) {
            const float4* ev = (const float4*)(emb + ((size_t)c * 16 + cats[a][c]) * DDIM);
            float4 e4 = __ldg(&ev[tx]);
            v.x += e4.x; v.y += e4.y; v.z += e4.z; v.w += e4.w;
        }
        ((float4*)out)[(size_t)row * 32 + tx] = v;
    }
}

// ---------------- CSR build ----------------
__global__ void hist_kernel(const int* __restrict__ dst, int* __restrict__ cnt) {
    int e = blockIdx.x * blockDim.x + threadIdx.x;
    if (e < N_BONDS) atomicAdd(&cnt[__ldg(&dst[e])], 1);
}
__global__ __launch_bounds__(1024) void csr_scan_kernel(const int* __restrict__ cnt,
                                                        int* __restrict__ rowptr) {
    __shared__ int part[1024];
    int t = threadIdx.x;
    const int CH = (N_ATOMS + 1023) / 1024;
    int base = t * CH;
    int s = 0;
    for (int i = 0; i < CH; i++) {
        int idx = base + i;
        if (idx < N_ATOMS) s += cnt[idx];
    }
    part[t] = s;
    __syncthreads();
    for (int off = 1; off < 1024; off <<= 1) {
        int v = (t >= off) ? part[t - off] : 0;
        __syncthreads();
        part[t] += v;
        __syncthreads();
    }
    int run = (t == 0) ? 0 : part[t - 1];
    for (int i = 0; i < CH; i++) {
        int idx = base + i;
        if (idx < N_ATOMS) { rowptr[idx] = run; run += cnt[idx]; }
    }
    if (t == 1023) rowptr[N_ATOMS] = part[1023];
}
__global__ void csr_scatter_kernel(const int* __restrict__ src, const int* __restrict__ dst,
                                   const int* __restrict__ rowptr, int* __restrict__ cur,
                                   int* __restrict__ csr_src, int* __restrict__ csr_eid) {
    int e = blockIdx.x * blockDim.x + threadIdx.x;
    if (e >= N_BONDS) return;
    int d = __ldg(&dst[e]);
    int pos = __ldg(&rowptr[d]) + atomicAdd(&cur[d], 1);
    csr_src[pos] = __ldg(&src[e]);
    csr_eid[pos] = e;
}

__global__ __launch_bounds__(128) void csr_gather_kernel(
    const float* __restrict__ node, const float* __restrict__ edge,
    const int* __restrict__ rowptr, const int* __restrict__ csr_src,
    const int* __restrict__ csr_eid, float* __restrict__ agg, int shift) {
    int a = blockIdx.x * 4 + (threadIdx.x >> 5);
    int lane = threadIdx.x & 31;
    if (a >= N_ATOMS) return;
    int beg = __ldg(&rowptr[a]);
    int end = __ldg(&rowptr[a + 1]);
    float4 acc = make_float4(0.f, 0.f, 0.f, 0.f);
    for (int j = beg; j < end; j++) {
        int s = __ldg(&csr_src[j]);
        int e = __ldg(&csr_eid[j]);
        float4 nv = __ldg(&((const float4*)node)[(size_t)s * 32 + lane]);
        float4 ev = __ldg(&((const float4*)edge)[(size_t)(e >> shift) * 32 + lane]);
        acc.x += nv.x + ev.x; acc.y += nv.y + ev.y;
        acc.z += nv.z + ev.z; acc.w += nv.w + ev.w;
    }
    ((float4*)agg)[(size_t)a * 32 + lane] = acc;
}

// ---------------- BA feature build ----------------
__global__ void f1_build_kernel(const int* __restrict__ bond_cat,
                                const float* __restrict__ rbond,
                                float* __restrict__ feat) {
    int s = blockIdx.x * blockDim.x + threadIdx.x;
    if (s >= N_HALF) return;
    float* row = feat + (size_t)(50000 + s) * KF;
#pragma unroll
    for (int c = 0; c < 3; c++) {
        int v = __ldg(&bond_cat[(size_t)(2 * s) * 3 + c]);
        row[c * 16 + v] = 1.f;
    }
    const float4* rb = (const float4*)(rbond + (size_t)(2 * s) * K_BOND);
#pragma unroll
    for (int q = 0; q < 5; q++) ((float4*)(row + 48))[q] = __ldg(&rb[q]);
    row[100] = 1.f;
}

__global__ void fsum_scatter_kernel(const int* __restrict__ bond_cat,
                                    const float* __restrict__ rbond,
                                    const float* __restrict__ rangle,
                                    const int* __restrict__ src,
                                    const int* __restrict__ dst,
                                    float* __restrict__ feat) {
    int a = blockIdx.x * blockDim.x + threadIdx.x;
    if (a >= N_ANGLES) return;
    int s = __ldg(&src[a]);
    int d = __ldg(&dst[a]);
    float* row = feat + (size_t)d * KF;
#pragma unroll
    for (int c = 0; c < 3; c++) {
        int v = __ldg(&bond_cat[(size_t)(2 * s) * 3 + c]);
        red_add1(row + c * 16 + v, 1.f);
    }
    const float4* rb = (const float4*)(rbond + (size_t)(2 * s) * K_BOND);
#pragma unroll
    for (int q = 0; q < 5; q++) red_add_v4(row + 48 + q * 4, __ldg(&rb[q]));
    const float4* ra = (const float4*)(rangle + (size_t)a * K_ANGLE);
#pragma unroll
    for (int q = 0; q < 8; q++) red_add_v4(row + 68 + q * 4, __ldg(&ra[q]));
    red_add_v2(row + 100, 1.f, 1.f);
}

// assemble Wcat^T fp32 per layer: [l][n][k], n in [0,128), k in [0,112) (zeros padded)
__global__ void wcat_prep_kernel(const float* __restrict__ layer_bond_emb,
                                 const float* __restrict__ layer_bond_rbf_w,
                                 const float* __restrict__ layer_bond_rbf_b,
                                 const float* __restrict__ layer_angle_rbf_w,
                                 const float* __restrict__ layer_angle_rbf_b,
                                 float* __restrict__ wcat) {
    int gid = blockIdx.x * blockDim.x + threadIdx.x;
    if (gid >= 8 * 128 * KF) return;
    int l = gid / (128 * KF);
    int r = gid % (128 * KF);
    int n = r / KF, k = r % KF;
    float v = 0.f;
    if (k < 48)        v = __ldg(&layer_bond_emb[(((size_t)l * 3 + (k >> 4)) * 16 + (k & 15)) * DDIM + n]);
    else if (k < 68)   v = __ldg(&layer_bond_rbf_w[((size_t)l * K_BOND + (k - 48)) * DDIM + n]);
    else if (k < 100)  v = __ldg(&layer_angle_rbf_w[((size_t)l * K_ANGLE + (k - 68)) * DDIM + n]);
    else if (k == 100) v = __ldg(&layer_bond_rbf_b[(size_t)l * DDIM + n]);
    else if (k == 101) v = __ldg(&layer_angle_rbf_b[(size_t)l * DDIM + n]);
    wcat[gid] = v;
}

// C[M,128] = A[M,112] @ Wn^T via bf16x3 mma; conversions in-kernel (validated in R11).
__global__ __launch_bounds__(256, 2) void feat_mma_kernel(
    const float* __restrict__ A, const float* __restrict__ Wn,
    float* __restrict__ C, int M) {
    extern __shared__ unsigned char smem[];
    int tid = threadIdx.x;
    int wid = tid >> 5, lid = tid & 31;
    int gid = lid >> 2, tig = lid & 3;
    int row0 = blockIdx.x * 128;

    uint32_t* Ah = (uint32_t*)(smem + FM_AHI);
    uint32_t* Al = (uint32_t*)(smem + FM_ALO);
    uint32_t* Bh = (uint32_t*)(smem + FM_BHI);
    uint32_t* Bl = (uint32_t*)(smem + FM_BLO);

    for (int t = tid; t < 1792; t += 256) {
        int r = t / 14, c4 = t % 14;
        float4 f0 = make_float4(0.f, 0.f, 0.f, 0.f), f1 = f0;
        if (row0 + r < M) {
            const float4* ap = (const float4*)(A + (size_t)(row0 + r) * KF + c4 * 8);
            f0 = __ldg(ap); f1 = __ldg(ap + 1);
        }
        float f[8] = {f0.x, f0.y, f0.z, f0.w, f1.x, f1.y, f1.z, f1.w};
        uint32_t ph[4], pl[4];
#pragma unroll
        for (int q = 0; q < 4; q++) {
            ph[q] = pack_bf16(f[2 * q], f[2 * q + 1]);
            pl[q] = pack_bf16(f[2 * q] - lo_f(ph[q]), f[2 * q + 1] - hi_f(ph[q]));
        }
        *(uint4*)(Ah + r * 60 + c4 * 4) = make_uint4(ph[0], ph[1], ph[2], ph[3]);
        *(uint4*)(Al + r * 60 + c4 * 4) = make_uint4(pl[0], pl[1], pl[2], pl[3]);
    }

    float2* C2 = (float2*)C;
#pragma unroll 1
    for (int nc = 0; nc < 2; nc++) {
        if (nc) __syncthreads();
        for (int t = tid; t < 896; t += 256) {
            int r = t / 14, c4 = t % 14;
            const float4* wp = (const float4*)(Wn + (size_t)(nc * 64 + r) * KF + c4 * 8);
            float4 f0 = __ldg(wp), f1 = __ldg(wp + 1);
            float f[8] = {f0.x, f0.y, f0.z, f0.w, f1.x, f1.y, f1.z, f1.w};
            uint32_t ph[4], pl[4];
#pragma unroll
            for (int q = 0; q < 4; q++) {
                ph[q] = pack_bf16(f[2 * q], f[2 * q + 1]);
                pl[q] = pack_bf16(f[2 * q] - lo_f(ph[q]), f[2 * q + 1] - hi_f(ph[q]));
            }
            *(uint4*)(Bh + r * 60 + c4 * 4) = make_uint4(ph[0], ph[1], ph[2], ph[3]);
            *(uint4*)(Bl + r * 60 + c4 * 4) = make_uint4(pl[0], pl[1], pl[2], pl[3]);
        }
        __syncthreads();

        float acc[8][4];
#pragma unroll
        for (int ns = 0; ns < 8; ns++)
#pragma unroll
            for (int q = 0; q < 4; q++) acc[ns][q] = 0.f;

#pragma unroll 1
        for (int pass = 0; pass < 3; pass++) {
            const uint32_t* Ap = (pass == 2) ? Al : Ah;
            const uint32_t* Bp = (pass == 1) ? Bl : Bh;
#pragma unroll
            for (int k16 = 0; k16 < 7; k16++) {
                int kw = k16 * 8 + tig;
                const uint32_t* ra = Ap + (wid * 16 + gid) * 60 + kw;
                uint32_t a0 = ra[0], a1 = ra[8 * 60], a2 = ra[4], a3 = ra[8 * 60 + 4];
#pragma unroll
                for (int ns = 0; ns < 8; ns++) {
                    const uint32_t* rb = Bp + (ns * 8 + gid) * 60 + kw;
                    mma16816(acc[ns], a0, a1, a2, a3, rb[0], rb[4]);
                }
            }
        }
        int rlo = row0 + wid * 16 + gid, rhi = rlo + 8;
#pragma unroll
        for (int ns = 0; ns < 8; ns++) {
            int c0 = nc * 64 + ns * 8 + 2 * tig;
            if (rlo < M) C2[(size_t)rlo * 64 + (c0 >> 1)] = make_float2(acc[ns][0], acc[ns][1]);
            if (rhi < M) C2[(size_t)rhi * 64 + (c0 >> 1)] = make_float2(acc[ns][2], acc[ns][3]);
        }
    }
}

// ---------------- tensor-core fused MLP + LN (R14, byte-identical; DUP templated) ----------------
template <int DUP>
__global__ __launch_bounds__(256, 1) void mlp_mma_kernel(
    const float* __restrict__ X, const float* __restrict__ res,
    const float* __restrict__ b1, const float* __restrict__ b2,
    const float* __restrict__ lng, const float* __restrict__ lnb,
    const unsigned char* __restrict__ wimg,
    float* __restrict__ out, int N, float inv_sqrt_n,
    float* __restrict__ out_dup) {
    extern __shared__ unsigned char smem[];
    int tid = threadIdx.x;
    int wid = tid >> 5, lid = tid & 31;
    int gid = lid >> 2, tig = lid & 3;
    int row0 = blockIdx.x * 128;

    float* hb1 = (float*)(smem + OFF_HB1);
    float* hb2 = (float*)(smem + OFF_HB2);
    float* hg  = (float*)(smem + OFF_HG);
    float* hbt = (float*)(smem + OFF_HBT);
    hb1[tid] = __ldg(&b1[tid]);
    if (tid < 128) { hb2[tid] = __ldg(&b2[tid]); hg[tid] = __ldg(&lng[tid]); hbt[tid] = __ldg(&lnb[tid]); }

    for (int t = tid; t < 2048; t += 256) {
        int r = t >> 4;
        int k0 = (t & 15) * 8;
        float4 f0 = make_float4(0.f, 0.f, 0.f, 0.f), f1 = f0;
        if (row0 + r < N) {
            const float4* xp = (const float4*)(X + (size_t)(row0 + r) * 128 + k0);
            f0 = __ldg(xp); f1 = __ldg(xp + 1);
        }
        float f[8] = {f0.x, f0.y, f0.z, f0.w, f1.x, f1.y, f1.z, f1.w};
        uint32_t ph[4], pl[4];
#pragma unroll
        for (int q = 0; q < 4; q++) {
            ph[q] = pack_bf16(f[2 * q], f[2 * q + 1]);
            pl[q] = pack_bf16(f[2 * q] - lo_f(ph[q]), f[2 * q + 1] - hi_f(ph[q]));
        }
        int byt = r * 272 + k0 * 2;
        *(uint4*)(smem + ARENA + OFF_XHI + byt) = make_uint4(ph[0], ph[1], ph[2], ph[3]);
        *(uint4*)(smem + ARENA + OFF_XLO + byt) = make_uint4(pl[0], pl[1], pl[2], pl[3]);
    }
    for (int i = tid; i < 4096; i += 256) {
        int n = i >> 4, c = i & 15;
        int dst = n * 272 + c * 16;
        *(uint4*)(smem + ARENA + OFF_W1HI + dst) = __ldg(&((const uint4*)wimg)[i]);
        *(uint4*)(smem + ARENA + OFF_W1LO + dst) = __ldg(&((const uint4*)(wimg + 65536))[i]);
    }
    __syncthreads();

    const int mwarp = wid >> 1, nwarp = wid & 1;
    float acc[4][2][4][4];
#pragma unroll
    for (int ch = 0; ch < 4; ch++)
#pragma unroll
        for (int ms = 0; ms < 2; ms++)
#pragma unroll
            for (int ns = 0; ns < 4; ns++)
#pragma unroll
                for (int q = 0; q < 4; q++) acc[ch][ms][ns][q] = 0.f;

#pragma unroll 1
    for (int pass = 0; pass < 3; pass++) {
        const uint32_t* Ap = (const uint32_t*)(smem + ARENA + (pass == 2 ? OFF_XLO : OFF_XHI));
        const uint32_t* Bp = (const uint32_t*)(smem + ARENA + (pass == 1 ? OFF_W1LO : OFF_W1HI));
#pragma unroll
        for (int k16 = 0; k16 < 8; k16++) {
            int kw = k16 * 8 + tig;
            uint32_t a[2][4];
#pragma unroll
            for (int ms = 0; ms < 2; ms++) {
                const uint32_t* r0p = Ap + (mwarp * 32 + ms * 16 + gid) * 68 + kw;
                a[ms][0] = r0p[0]; a[ms][1] = r0p[8 * 68];
                a[ms][2] = r0p[4]; a[ms][3] = r0p[8 * 68 + 4];
            }
#pragma unroll
            for (int ch = 0; ch < 4; ch++)
#pragma unroll
                for (int ns = 0; ns < 4; ns++) {
                    const uint32_t* br = Bp + (ch * 64 + nwarp * 32 + ns * 8 + gid) * 68 + kw;
                    uint32_t bb0 = br[0], bb1 = br[4];
#pragma unroll
                    for (int ms = 0; ms < 2; ms++)
                        mma16816(acc[ch][ms][ns], a[ms][0], a[ms][1], a[ms][2], a[ms][3], bb0, bb1);
                }
        }
    }
    __syncthreads();

    {
        uint32_t* Hh = (uint32_t*)(smem + ARENA + OFF_H1HI);
        uint32_t* Hl = (uint32_t*)(smem + ARENA + OFF_H1LO);
#pragma unroll
        for (int ch = 0; ch < 4; ch++)
#pragma unroll
            for (int ms = 0; ms < 2; ms++)
#pragma unroll
                for (int ns = 0; ns < 4; ns++) {
                    int c0 = ch * 64 + nwarp * 32 + ns * 8 + 2 * tig;
                    float bb0 = hb1[c0], bb1 = hb1[c0 + 1];
                    int rlo = mwarp * 32 + ms * 16 + gid;
                    float v0 = fmaxf(acc[ch][ms][ns][0] + bb0, 0.f);
                    float v1 = fmaxf(acc[ch][ms][ns][1] + bb1, 0.f);
                    float v2 = fmaxf(acc[ch][ms][ns][2] + bb0, 0.f);
                    float v3 = fmaxf(acc[ch][ms][ns][3] + bb1, 0.f);
                    uint32_t p0 = pack_bf16(v0, v1);
                    uint32_t q0 = pack_bf16(v0 - lo_f(p0), v1 - hi_f(p0));
                    uint32_t p1 = pack_bf16(v2, v3);
                    uint32_t q1 = pack_bf16(v2 - lo_f(p1), v3 - hi_f(p1));
                    Hh[rlo * 132 + (c0 >> 1)] = p0;
                    Hl[rlo * 132 + (c0 >> 1)] = q0;
                    Hh[(rlo + 8) * 132 + (c0 >> 1)] = p1;
                    Hl[(rlo + 8) * 132 + (c0 >> 1)] = q1;
                }
    }

    float acc2[2][8][4];
#pragma unroll
    for (int wc = 0; wc < 2; wc++)
#pragma unroll
        for (int ns = 0; ns < 8; ns++)
#pragma unroll
            for (int q = 0; q < 4; q++) acc2[wc][ns][q] = 0.f;

#pragma unroll 1
    for (int wc = 0; wc < 2; wc++) {
        __syncthreads();
        for (int i = tid; i < 2048; i += 256) {
            int n = i >> 5, c = i & 31;
            int dst = n * 528 + c * 16;
            *(uint4*)(smem + ARENA + OFF_W2HI + dst) =
                __ldg(&((const uint4*)(wimg + 131072 + wc * 32768))[i]);
            *(uint4*)(smem + ARENA + OFF_W2LO + dst) =
                __ldg(&((const uint4*)(wimg + 196608 + wc * 32768))[i]);
        }
        __syncthreads();
#pragma unroll 1
        for (int pass = 0; pass < 3; pass++) {
            const uint32_t* Ap = (const uint32_t*)(smem + ARENA + (pass == 2 ? OFF_H1LO : OFF_H1HI));
            const uint32_t* Bp = (const uint32_t*)(smem + ARENA + (pass == 1 ? OFF_W2LO : OFF_W2HI));
#pragma unroll
            for (int k16 = 0; k16 < 16; k16++) {
                int kw = k16 * 8 + tig;
                const uint32_t* r0p = Ap + (wid * 16 + gid) * 132 + kw;
                uint32_t a0 = r0p[0], a1 = r0p[8 * 132], a2 = r0p[4], a3 = r0p[8 * 132 + 4];
#pragma unroll
                for (int ns = 0; ns < 8; ns++) {
                    const uint32_t* br = Bp + (ns * 8 + gid) * 132 + kw;
                    mma16816(acc2[wc][ns], a0, a1, a2, a3, br[0], br[4]);
                }
            }
        }
    }

    float s0 = 0.f, q0 = 0.f, s1 = 0.f, q1 = 0.f;
#pragma unroll
    for (int wc = 0; wc < 2; wc++)
#pragma unroll
        for (int ns = 0; ns < 8; ns++) {
            int c0 = wc * 64 + ns * 8 + 2 * tig;
            acc2[wc][ns][0] += hb2[c0];
            acc2[wc][ns][1] += hb2[c0 + 1];
            acc2[wc][ns][2] += hb2[c0];
            acc2[wc][ns][3] += hb2[c0 + 1];
            s0 += acc2[wc][ns][0] + acc2[wc][ns][1];
            q0 += acc2[wc][ns][0] * acc2[wc][ns][0] + acc2[wc][ns][1] * acc2[wc][ns][1];
            s1 += acc2[wc][ns][2] + acc2[wc][ns][3];
            q1 += acc2[wc][ns][2] * acc2[wc][ns][2] + acc2[wc][ns][3] * acc2[wc][ns][3];
        }
#pragma unroll
    for (int off = 1; off <= 2; off <<= 1) {
        s0 += __shfl_xor_sync(0xffffffffu, s0, off);
        q0 += __shfl_xor_sync(0xffffffffu, q0, off);
        s1 += __shfl_xor_sync(0xffffffffu, s1, off);
        q1 += __shfl_xor_sync(0xffffffffu, q1, off);
    }
    float mu0 = s0 * (1.f / 128.f), mu1 = s1 * (1.f / 128.f);
    float rs0 = rsqrtf(q0 * (1.f / 128.f) - mu0 * mu0 + 1e-5f);
    float rs1 = rsqrtf(q1 * (1.f / 128.f) - mu1 * mu1 + 1e-5f);
    int rlo = row0 + wid * 16 + gid, rhi = rlo + 8;
    const float2* res2 = (const float2*)res;
    float2* out2 = (float2*)out;
    float2* dup2 = (float2*)out_dup;
#pragma unroll
    for (int wc = 0; wc < 2; wc++)
#pragma unroll
        for (int ns = 0; ns < 8; ns++) {
            int c0 = wc * 64 + ns * 8 + 2 * tig;
            float g0 = hg[c0], g1 = hg[c0 + 1], t0 = hbt[c0], t1 = hbt[c0 + 1];
            if (rlo < N) {
                float2 rr = __ldg(&res2[(size_t)rlo * 64 + (c0 >> 1)]);
                float o0 = fmaxf(((acc2[wc][ns][0] - mu0) * rs0 * g0 + t0) * inv_sqrt_n, 0.f) + rr.x;
                float o1 = fmaxf(((acc2[wc][ns][1] - mu0) * rs0 * g1 + t1) * inv_sqrt_n, 0.f) + rr.y;
                float2 ov = make_float2(o0, o1);
                out2[(size_t)rlo * 64 + (c0 >> 1)] = ov;
                if (DUP) {
                    dup2[(size_t)(2 * rlo) * 64 + (c0 >> 1)] = ov;
                    dup2[(size_t)(2 * rlo + 1) * 64 + (c0 >> 1)] = ov;
                }
            }
            if (rhi < N) {
                float2 rr = __ldg(&res2[(size_t)rhi * 64 + (c0 >> 1)]);
                float o2 = fmaxf(((acc2[wc][ns][2] - mu1) * rs1 * g0 + t0) * inv_sqrt_n, 0.f) + rr.x;
                float o3 = fmaxf(((acc2[wc][ns][3] - mu1) * rs1 * g1 + t1) * inv_sqrt_n, 0.f) + rr.y;
                float2 ov = make_float2(o2, o3);
                out2[(size_t)rhi * 64 + (c0 >> 1)] = ov;
                if (DUP) {
                    dup2[(size_t)(2 * rhi) * 64 + (c0 >> 1)] = ov;
                    dup2[(size_t)(2 * rhi + 1) * 64 + (c0 >> 1)] = ov;
                }
            }
        }
}

__global__ void graph_zero_kernel(float* g) { g[threadIdx.x] = 0.f; }

__global__ void graph_mean_kernel(const float* __restrict__ node, float* __restrict__ g) {
    int d = threadIdx.x;
    int r0 = blockIdx.x * 125;
    float s = 0.f;
    for (int i = 0; i < 125; i++) s += node[(size_t)(r0 + i) * DDIM + d];
    atomicAdd(&g[d], s * (1.f / 30000.f));
}

__global__ void wprep_kernel(const float* __restrict__ ab_w1, const float* __restrict__ ab_w2,
                             const float* __restrict__ ba_w1, const float* __restrict__ ba_w2,
                             unsigned char* __restrict__ wimg) {
    int gid = blockIdx.x * blockDim.x + threadIdx.x;
    if (gid >= 16 * 65536) return;
    int mlp = gid >> 16;
    int e = gid & 65535;
    int is_ba = mlp >= 8, l = mlp & 7;
    int is_w2 = e >= 32768;
    int e2 = e & 32767;
    float v;
    int dstoff;
    if (!is_w2) {
        int n = e2 >> 7, k = e2 & 127;
        const float* W = (is_ba ? ba_w1 : ab_w1) + (size_t)l * DDIM * HDIM;
        v = __ldg(&W[(size_t)k * HDIM + n]);
        dstoff = n * 128 + k;
    } else {
        int n = e2 >> 8, k = e2 & 255;
        const float* W = (is_ba ? ba_w2 : ab_w2) + (size_t)l * HDIM * DDIM;
        v = __ldg(&W[(size_t)k * DDIM + n]);
        dstoff = n * 256 + k;
    }
    __nv_bfloat16 hi = __float2bfloat16(v);
    __nv_bfloat16 lo = __float2bfloat16(v - __bfloat162float(hi));
    unsigned char* base = wimg + (size_t)mlp * 262144 + (is_w2 ? 131072 : 0);
    *(__nv_bfloat16*)(base + dstoff * 2)         = hi;
    *(__nv_bfloat16*)(base + 65536 + dstoff * 2) = lo;
}

// ---------------- host ----------------
extern "C" void kernel_launch(void* const* d_in, const int* in_sizes, int n_in,
                              void* d_out, int out_size) {
    const int*   atom_cat          = (const int*)d_in[0];
    const int*   bond_cat          = (const int*)d_in[1];
    const float* bond_float        = (const float*)d_in[2];
    const float* angle_float       = (const float*)d_in[3];
    const int*   ab_src            = (const int*)d_in[4];
    const int*   ab_dst            = (const int*)d_in[5];
    const int*   ba_src            = (const int*)d_in[6];
    const int*   ba_dst            = (const int*)d_in[7];
    const float* atom_emb          = (const float*)d_in[8];
    const float* bond_emb_init     = (const float*)d_in[9];
    const float* bond_rbf_w_init   = (const float*)d_in[10];
    const float* bond_rbf_b_init   = (const float*)d_in[11];
    const float* layer_bond_emb    = (const float*)d_in[12];
    const float* layer_bond_rbf_w  = (const float*)d_in[13];
    const float* layer_bond_rbf_b  = (const float*)d_in[14];
    const float* layer_angle_rbf_w = (const float*)d_in[15];
    const float* layer_angle_rbf_b = (const float*)d_in[16];
    const float* ab_w1 = (const float*)d_in[17];
    const float* ab_b1 = (const float*)d_in[18];
    const float* ab_w2 = (const float*)d_in[19];
    const float* ab_b2 = (const float*)d_in[20];
    const float* ab_ln_g = (const float*)d_in[21];
    const float* ab_ln_b = (const float*)d_in[22];
    const float* ba_w1 = (const float*)d_in[23];
    const float* ba_b1 = (const float*)d_in[24];
    const float* ba_w2 = (const float*)d_in[25];
    const float* ba_b2 = (const float*)d_in[26];
    const float* ba_ln_g = (const float*)d_in[27];
    const float* ba_ln_b = (const float*)d_in[28];

    float *node, *edge0, *half, *agg, *r_angle, *r_bond, *feat, *bab, *wcatn;
    unsigned char *wimg;
    int *cnt, *cur, *rowptr, *csr_src, *csr_eid;
    cudaGetSymbolAddress((void**)&node,    g_node);
    cudaGetSymbolAddress((void**)&edge0,   g_edge0);
    cudaGetSymbolAddress((void**)&half,    g_half);
    cudaGetSymbolAddress((void**)&agg,     g_agg);
    cudaGetSymbolAddress((void**)&r_angle, g_r_angle);
    cudaGetSymbolAddress((void**)&r_bond,  g_r_bond);
    cudaGetSymbolAddress((void**)&wimg,    g_wimg);
    cudaGetSymbolAddress((void**)&feat,    g_feat);
    cudaGetSymbolAddress((void**)&wcatn,   g_wcatn);
    cudaGetSymbolAddress((void**)&bab,     g_bab);
    cudaGetSymbolAddress((void**)&cnt,     g_cnt);
    cudaGetSymbolAddress((void**)&cur,     g_cur);
    cudaGetSymbolAddress((void**)&rowptr,  g_rowptr);
    cudaGetSymbolAddress((void**)&csr_src, g_csr_src);
    cudaGetSymbolAddress((void**)&csr_eid, g_csr_eid);

    cudaFuncSetAttribute(mlp_mma_kernel<0>, cudaFuncAttributeMaxDynamicSharedMemorySize, MLP_SMEM);
    cudaFuncSetAttribute(mlp_mma_kernel<1>, cudaFuncAttributeMaxDynamicSharedMemorySize, MLP_SMEM);
    cudaFuncSetAttribute(feat_mma_kernel, cudaFuncAttributeMaxDynamicSharedMemorySize, FM_SMEM);

    const float inv_a = 1.0f / sqrtf((float)N_ATOMS);
    const float inv_h = 1.0f / sqrtf((float)N_HALF);

    // ---- one-time prep (single stream, proven schedule) ----
    wprep_kernel<<<4096, 256>>>(ab_w1, ab_w2, ba_w1, ba_w2, wimg);
    rbf_pre_kernel<<<(N_ANGLES * K_ANGLE + 255) / 256, 256>>>(angle_float, r_angle, N_ANGLES, K_ANGLE);
    rbf_pre_kernel<<<(N_BONDS * K_BOND + 255) / 256, 256>>>(bond_float, r_bond, N_BONDS, K_BOND);
    node_embed_kernel<<<N_ATOMS, 128>>>(atom_cat, atom_emb, node);
    bond_embed_kernel<<<(N_BONDS + 31) / 32, 128>>>(bond_cat, r_bond, bond_emb_init,
                                                    bond_rbf_w_init, bond_rbf_b_init,
                                                    edge0, N_BONDS);
    zeroi_kernel<<<(N_ATOMS + 255) / 256, 256>>>(cnt, N_ATOMS);
    zeroi_kernel<<<(N_ATOMS + 255) / 256, 256>>>(cur, N_ATOMS);
    hist_kernel<<<(N_BONDS + 255) / 256, 256>>>(ab_dst, cnt);
    csr_scan_kernel<<<1, 1024>>>(cnt, rowptr);
    csr_scatter_kernel<<<(N_BONDS + 255) / 256, 256>>>(ab_src, ab_dst, rowptr, cur,
                                                       csr_src, csr_eid);
    zero4_kernel<<<(100000 * KF / 4 + 255) / 256, 256>>>((float4*)feat, 100000 * KF / 4);
    f1_build_kernel<<<(N_HALF + 255) / 256, 256>>>(bond_cat, r_bond, feat);
    fsum_scatter_kernel<<<(N_ANGLES + 127) / 128, 128>>>(bond_cat, r_bond, r_angle,
                                                         ba_src, ba_dst, feat);
    wcat_prep_kernel<<<(8 * 128 * KF + 255) / 256, 256>>>(
        layer_bond_emb, layer_bond_rbf_w, layer_bond_rbf_b,
        layer_angle_rbf_w, layer_angle_rbf_b, wcatn);

    float* out = (float*)d_out;
    float* out_node = out;
    float* out_edge = out + (size_t)N_ATOMS * DDIM;
    for (int l = 0; l < NLAYERS; l++) {
        // --- AB GNN: CSR gather + MLP (R14 path) ---
        csr_gather_kernel<<<(N_ATOMS + 3) / 4, 128>>>(
            node, (l == 0) ? edge0 : half, rowptr, csr_src, csr_eid,
            agg, (l == 0) ? 0 : 1);
        mlp_mma_kernel<0><<<(N_ATOMS + 127) / 128, 256, MLP_SMEM>>>(
            agg, node,
            ab_b1 + (size_t)l * HDIM, ab_b2 + (size_t)l * DDIM,
            ab_ln_g + (size_t)l * DDIM, ab_ln_b + (size_t)l * DDIM,
            wimg + (size_t)l * 262144,
            (l == NLAYERS - 1) ? out_node : node, N_ATOMS, inv_a, nullptr);

        // --- BA GNN: bf16 mma feature GEMM (validated R11) + MLP ---
        feat_mma_kernel<<<(100000 + 127) / 128, 256, FM_SMEM>>>(
            feat, wcatn + (size_t)l * 128 * KF, bab, 100000);
        if (l == NLAYERS - 1) {
            mlp_mma_kernel<1><<<(N_HALF + 127) / 128, 256, MLP_SMEM>>>(
                bab, bab + (size_t)50000 * DDIM,
                ba_b1 + (size_t)l * HDIM, ba_b2 + (size_t)l * DDIM,
                ba_ln_g + (size_t)l * DDIM, ba_ln_b + (size_t)l * DDIM,
                wimg + (size_t)(8 + l) * 262144,
                half, N_HALF, inv_h, out_edge);
        } else {
            mlp_mma_kernel<0><<<(N_HALF + 127) / 128, 256, MLP_SMEM>>>(
                bab, bab + (size_t)50000 * DDIM,
                ba_b1 + (size_t)l * HDIM, ba_b2 + (size_t)l * DDIM,
                ba_ln_g + (size_t)l * DDIM, ba_ln_b + (size_t)l * DDIM,
                wimg + (size_t)(8 + l) * 262144,
                half, N_HALF, inv_h, nullptr);
        }
    }

    // --- graph mean (reads node result from d_out) ---
    float* gout = out + (size_t)N_ATOMS * DDIM + (size_t)N_BONDS * DDIM;
    graph_zero_kernel<<<1, 128>>>(gout);
    graph_mean_kernel<<<240, 128>>>(out_node, gout);
}